// round 7
// baseline (speedup 1.0000x reference)
#include <cuda_runtime.h>
#include <cuda_bf16.h>
#include <mma.h>
#include <math.h>

using namespace nvcuda;

// Problem constants (fixed shapes)
#define BSZ   4
#define SEQ   1024
#define DM    512
#define NH    8
#define DQ    64
#define M_TOT (BSZ*SEQ)     // 4096 tokens
#define N_TOT (2*DM)        // 1024: [Q feats | K feats]
#define NBH   (BSZ*NH)      // 32 (batch,head) pairs

// -------------------- device scratch --------------------
__device__ float g_QK[M_TOT * N_TOT];   // 16 MB: per token, 512 Q feats then 512 K feats
__device__ float g_Sf[NBH * SEQ];
__device__ float g_Sb[NBH * SEQ];
__device__ float g_G [NBH * SEQ];       // exclusive prefix sums of g
__device__ float g_band[NBH * SEQ];     // ph_i

// -------------------- Kernel 1: fused cvt + bf16 WMMA GEMM, double-buffered ----
// C[m,n] = sum_k ctx[m,k] * Wcat[n,k]   (Wcat = [Wq ; Wk], row-major (1024,512))
#define BM   128
#define BN   128
#define BKK  32
#define KPAD 40   // 80-byte rows: uint4-aligned, breaks WMMA bank conflicts

__global__ __launch_bounds__(256) void gemm_kernel(
    const float* __restrict__ ctx,
    const float* __restrict__ Wq,
    const float* __restrict__ Wk)
{
    __shared__ __nv_bfloat16 As [2][BM][KPAD];
    __shared__ __nv_bfloat16 Bsm[2][BN][KPAD];
    const int bn = blockIdx.x;           // 0..7
    const int bm = blockIdx.y;           // 0..31
    const int tid = threadIdx.x;
    const int warp = tid >> 5;
    const int wm = warp & 3;             // 4 warps along M
    const int wn = warp >> 2;            // 2 warps along N

    wmma::fragment<wmma::accumulator,16,16,16,float> acc[2][4];
    #pragma unroll
    for (int m = 0; m < 2; m++)
        #pragma unroll
        for (int n = 0; n < 4; n++)
            wmma::fill_fragment(acc[m][n], 0.0f);

    // per-thread load coordinates (same mapping as R2): 4 groups for A, 4 for B
    int rowA[4], gcA[4];
    const float* srcB[4];
    int rowB[4], gcB[4];
    #pragma unroll
    for (int j = 0; j < 4; j++) {
        int idx = tid + 256 * j;         // 1024 float4-groups per tile
        rowA[j] = idx >> 3;
        gcA[j]  = (idx & 7) * 4;
        rowB[j] = rowA[j];
        gcB[j]  = gcA[j];
        int wrow = bn*BN + rowB[j];
        srcB[j] = (wrow < DM) ? &Wq[(size_t)wrow*DM] : &Wk[(size_t)(wrow - DM)*DM];
    }
    const float* srcA = &ctx[(size_t)(bm*BM)*DM];

    // ---- preload tile 0 into buffer 0 ----
    #pragma unroll
    for (int j = 0; j < 4; j++) {
        float4 va = *(const float4*)&srcA[(size_t)rowA[j]*DM + gcA[j]];
        As[0][rowA[j]][gcA[j]+0] = __float2bfloat16(va.x);
        As[0][rowA[j]][gcA[j]+1] = __float2bfloat16(va.y);
        As[0][rowA[j]][gcA[j]+2] = __float2bfloat16(va.z);
        As[0][rowA[j]][gcA[j]+3] = __float2bfloat16(va.w);
        float4 vb = *(const float4*)&srcB[j][gcB[j]];
        Bsm[0][rowB[j]][gcB[j]+0] = __float2bfloat16(vb.x);
        Bsm[0][rowB[j]][gcB[j]+1] = __float2bfloat16(vb.y);
        Bsm[0][rowB[j]][gcB[j]+2] = __float2bfloat16(vb.z);
        Bsm[0][rowB[j]][gcB[j]+3] = __float2bfloat16(vb.w);
    }
    __syncthreads();

    const int NIT = DM / BKK;            // 16
    for (int kt = 0; kt < NIT; kt++) {
        const int cur = kt & 1;
        float4 av[4], bv[4];
        if (kt + 1 < NIT) {
            const int kg = (kt + 1) * BKK;
            #pragma unroll
            for (int j = 0; j < 4; j++) {
                av[j] = *(const float4*)&srcA[(size_t)rowA[j]*DM + kg + gcA[j]];
                bv[j] = *(const float4*)&srcB[j][kg + gcB[j]];
            }
        }

        #pragma unroll
        for (int kk = 0; kk < BKK; kk += 16) {
            wmma::fragment<wmma::matrix_a,16,16,16,__nv_bfloat16,wmma::row_major> af[2];
            wmma::fragment<wmma::matrix_b,16,16,16,__nv_bfloat16,wmma::col_major> bf[4];
            #pragma unroll
            for (int m = 0; m < 2; m++)
                wmma::load_matrix_sync(af[m], &As[cur][wm*32 + m*16][kk], KPAD);
            #pragma unroll
            for (int n = 0; n < 4; n++)
                wmma::load_matrix_sync(bf[n], &Bsm[cur][wn*64 + n*16][kk], KPAD);
            #pragma unroll
            for (int m = 0; m < 2; m++)
                #pragma unroll
                for (int n = 0; n < 4; n++)
                    wmma::mma_sync(acc[m][n], af[m], bf[n], acc[m][n]);
        }

        if (kt + 1 < NIT) {
            const int nxt = cur ^ 1;
            #pragma unroll
            for (int j = 0; j < 4; j++) {
                As[nxt][rowA[j]][gcA[j]+0] = __float2bfloat16(av[j].x);
                As[nxt][rowA[j]][gcA[j]+1] = __float2bfloat16(av[j].y);
                As[nxt][rowA[j]][gcA[j]+2] = __float2bfloat16(av[j].z);
                As[nxt][rowA[j]][gcA[j]+3] = __float2bfloat16(av[j].w);
                Bsm[nxt][rowB[j]][gcB[j]+0] = __float2bfloat16(bv[j].x);
                Bsm[nxt][rowB[j]][gcB[j]+1] = __float2bfloat16(bv[j].y);
                Bsm[nxt][rowB[j]][gcB[j]+2] = __float2bfloat16(bv[j].z);
                Bsm[nxt][rowB[j]][gcB[j]+3] = __float2bfloat16(bv[j].w);
            }
        }
        __syncthreads();
    }

    #pragma unroll
    for (int m = 0; m < 2; m++)
        #pragma unroll
        for (int n = 0; n < 4; n++)
            wmma::store_matrix_sync(
                &g_QK[(size_t)(bm*BM + wm*32 + m*16)*N_TOT + bn*BN + wn*64 + n*16],
                acc[m][n], N_TOT, wmma::mem_row_major);
}

// -------------------- Kernel 2: banded dot products (bias folded) --------------
__global__ __launch_bounds__(256) void band_kernel(
    const float* __restrict__ bq, const float* __restrict__ bk)
{
    int row  = blockIdx.x;               // b*SEQ + i
    int b    = row >> 10;
    int i    = row & (SEQ - 1);
    int h    = threadIdx.x >> 5;
    int lane = threadIdx.x & 31;
    int c    = h*DQ + lane*2;

    float2 qv  = *(const float2*)&g_QK[(size_t)row*N_TOT + c];
    float2 bqv = *(const float2*)&bq[c];
    float2 bkv = *(const float2*)&bk[c];
    float q0 = qv.x + bqv.x, q1 = qv.y + bqv.y;

    float sf = 0.f, sb = 0.f;
    if (i < SEQ-1) {
        float2 kv = *(const float2*)&g_QK[(size_t)(row+1)*N_TOT + DM + c];
        sf = q0*(kv.x + bkv.x) + q1*(kv.y + bkv.y);
    }
    if (i > 0) {
        float2 kv = *(const float2*)&g_QK[(size_t)(row-1)*N_TOT + DM + c];
        sb = q0*(kv.x + bkv.x) + q1*(kv.y + bkv.y);
    }
    #pragma unroll
    for (int off = 16; off; off >>= 1) {
        sf += __shfl_down_sync(0xffffffffu, sf, off);
        sb += __shfl_down_sync(0xffffffffu, sb, off);
    }
    if (lane == 0) {
        int idx = (b*NH + h)*SEQ + i;
        g_Sf[idx] = sf * (1.0f / DM);
        g_Sb[idx] = sb * (1.0f / DM);
    }
}

// -------------------- Kernel 3: softmax -> g -> block prefix scan --------------
__global__ __launch_bounds__(1024) void scan_kernel(const int* __restrict__ amask)
{
    int bh = blockIdx.x;
    int b  = bh >> 3;
    int t  = threadIdx.x;

    __shared__ float b_sh[SEQ];
    __shared__ float wsum[32];

    float sf = g_Sf[bh*SEQ + t];
    float sb = g_Sb[bh*SEQ + t];
    bool vf = (t < SEQ-1) && (amask[b*SEQ + t + 1] != 0);
    bool vb = (t > 0)     && (amask[b*SEQ + t - 1] != 0);

    float a, bb;
    if (vf | vb) {
        float m  = fmaxf(vf ? sf : -3.4e38f, vb ? sb : -3.4e38f);
        float ea = vf ? __expf(sf - m) : 0.f;
        float eb = vb ? __expf(sb - m) : 0.f;
        float den = ea + eb;
        a  = ea / den;
        bb = eb / den;
    } else {
        a = bb = 1.0f / SEQ;
    }
    b_sh[t] = bb;
    __syncthreads();

    float g = 0.f;
    if (t < SEQ-1) {
        float ph = sqrtf(a * b_sh[t+1] + 1e-9f);
        g_band[bh*SEQ + t] = ph;
        g = logf(ph + 1e-9f);
    }

    int lane = t & 31, wid = t >> 5;
    float incl = g;
    #pragma unroll
    for (int off = 1; off < 32; off <<= 1) {
        float n = __shfl_up_sync(0xffffffffu, incl, off);
        if (lane >= off) incl += n;
    }
    if (lane == 31) wsum[wid] = incl;
    __syncthreads();
    if (wid == 0) {
        float w = wsum[lane];
        #pragma unroll
        for (int off = 1; off < 32; off <<= 1) {
            float n = __shfl_up_sync(0xffffffffu, w, off);
            if (lane >= off) w += n;
        }
        wsum[lane] = w;
    }
    __syncthreads();
    float base = (wid > 0) ? wsum[wid-1] : 0.f;
    g_G[bh*SEQ + t] = base + incl - g;   // exclusive prefix: G[k] = sum_{j<k} g_j
}

// -------------------- Kernel 4: materialize outputs (R2 structure + __stcs) ----
__global__ __launch_bounds__(256) void out_kernel(float* __restrict__ out, int write_ph)
{
    const float SQRT_EPS = 3.1622776601683795e-5f;
    int row = blockIdx.x;                // bh*SEQ + i
    int bh  = row >> 10;
    int i   = row & (SEQ - 1);
    int k0  = threadIdx.x << 2;

    const float* Gp = g_G + bh*SEQ;
    float Gi = __ldg(&Gp[i]);
    float4 gk = *(const float4*)&Gp[k0];

    float4 o;
    {
        int k;
        k = k0 + 0; o.x = (k == i) ? SQRT_EPS : (__expf((k > i) ? gk.x - Gi : Gi - gk.x) + 1e-9f);
        k = k0 + 1; o.y = (k == i) ? SQRT_EPS : (__expf((k > i) ? gk.y - Gi : Gi - gk.y) + 1e-9f);
        k = k0 + 2; o.z = (k == i) ? SQRT_EPS : (__expf((k > i) ? gk.z - Gi : Gi - gk.z) + 1e-9f);
        k = k0 + 3; o.w = (k == i) ? SQRT_EPS : (__expf((k > i) ? gk.w - Gi : Gi - gk.w) + 1e-9f);
    }
    size_t off = (size_t)row * SEQ + k0;
    __stcs((float4*)(out + off), o);

    if (write_ph) {
        float4 p = make_float4(SQRT_EPS, SQRT_EPS, SQRT_EPS, SQRT_EPS);
        int d = (i - 1) - k0;
        if (d >= 0 && d < 4) {
            float v = g_band[bh*SEQ + i - 1];
            if (d == 0) p.x = v; else if (d == 1) p.y = v; else if (d == 2) p.z = v; else p.w = v;
        }
        d = (i + 1) - k0;
        if (d >= 0 && d < 4) {
            float v = g_band[bh*SEQ + i];
            if (d == 0) p.x = v; else if (d == 1) p.y = v; else if (d == 2) p.z = v; else p.w = v;
        }
        __stcs((float4*)(out + (size_t)NBH*SEQ*SEQ + off), p);
    }
}

// -------------------- launch ---------------------------------------------------
extern "C" void kernel_launch(void* const* d_in, const int* in_sizes, int n_in,
                              void* d_out, int out_size)
{
    const float* ctx   = (const float*)d_in[0];   // (4,1024,512) fp32
    const int*   amask = (const int*)  d_in[1];   // (4,1024) int32
    const float* Wq    = (const float*)d_in[2];   // (512,512)
    const float* bq    = (const float*)d_in[3];   // (512,)
    const float* Wk    = (const float*)d_in[4];   // (512,512)
    const float* bk    = (const float*)d_in[5];   // (512,)
    float* out = (float*)d_out;

    long long total = (long long)NBH * SEQ * SEQ;
    int write_ph = ((long long)out_size >= 2 * total) ? 1 : 0;

    dim3 ggrid(N_TOT / BN, M_TOT / BM);           // (8, 32)
    gemm_kernel<<<ggrid, 256>>>(ctx, Wq, Wk);
    band_kernel<<<M_TOT, 256>>>(bq, bk);
    scan_kernel<<<NBH, 1024>>>(amask);
    out_kernel<<<NBH * SEQ, 256>>>(out, write_ph);
}

// round 8
// speedup vs baseline: 1.0033x; 1.0033x over previous
#include <cuda_runtime.h>
#include <cuda_bf16.h>
#include <mma.h>
#include <math.h>

using namespace nvcuda;

// Problem constants (fixed shapes)
#define BSZ   4
#define SEQ   1024
#define DM    512
#define NH    8
#define DQ    64
#define M_TOT (BSZ*SEQ)     // 4096 tokens
#define N_TOT (2*DM)        // 1024: [Q feats | K feats]
#define NBH   (BSZ*NH)      // 32 (batch,head) pairs

// -------------------- device scratch --------------------
__device__ float g_QK[M_TOT * N_TOT];   // 16 MB: per token, 512 Q feats then 512 K feats
__device__ float g_Sf[NBH * SEQ];
__device__ float g_Sb[NBH * SEQ];
__device__ float g_G [NBH * SEQ];       // exclusive prefix sums of g
__device__ float g_band[NBH * SEQ];     // ph_i

// -------------------- Kernel 1: fused cvt + bf16 WMMA GEMM, double-buffered ----
// C[m,n] = sum_k ctx[m,k] * Wcat[n,k]   (Wcat = [Wq ; Wk], row-major (1024,512))
#define BM   128
#define BN   128
#define BKK  32
#define KPAD 40   // 80-byte rows: uint4-aligned, breaks WMMA bank conflicts

__global__ __launch_bounds__(256) void gemm_kernel(
    const float* __restrict__ ctx,
    const float* __restrict__ Wq,
    const float* __restrict__ Wk)
{
    __shared__ __nv_bfloat16 As [2][BM][KPAD];
    __shared__ __nv_bfloat16 Bsm[2][BN][KPAD];
    const int bn = blockIdx.x;           // 0..7
    const int bm = blockIdx.y;           // 0..31
    const int tid = threadIdx.x;
    const int warp = tid >> 5;
    const int wm = warp & 3;             // 4 warps along M
    const int wn = warp >> 2;            // 2 warps along N

    wmma::fragment<wmma::accumulator,16,16,16,float> acc[2][4];
    #pragma unroll
    for (int m = 0; m < 2; m++)
        #pragma unroll
        for (int n = 0; n < 4; n++)
            wmma::fill_fragment(acc[m][n], 0.0f);

    // per-thread load coordinates (same mapping as R2): 4 groups for A, 4 for B
    int rowA[4], gcA[4];
    const float* srcB[4];
    int rowB[4], gcB[4];
    #pragma unroll
    for (int j = 0; j < 4; j++) {
        int idx = tid + 256 * j;         // 1024 float4-groups per tile
        rowA[j] = idx >> 3;
        gcA[j]  = (idx & 7) * 4;
        rowB[j] = rowA[j];
        gcB[j]  = gcA[j];
        int wrow = bn*BN + rowB[j];
        srcB[j] = (wrow < DM) ? &Wq[(size_t)wrow*DM] : &Wk[(size_t)(wrow - DM)*DM];
    }
    const float* srcA = &ctx[(size_t)(bm*BM)*DM];

    // ---- preload tile 0 into buffer 0 ----
    #pragma unroll
    for (int j = 0; j < 4; j++) {
        float4 va = *(const float4*)&srcA[(size_t)rowA[j]*DM + gcA[j]];
        As[0][rowA[j]][gcA[j]+0] = __float2bfloat16(va.x);
        As[0][rowA[j]][gcA[j]+1] = __float2bfloat16(va.y);
        As[0][rowA[j]][gcA[j]+2] = __float2bfloat16(va.z);
        As[0][rowA[j]][gcA[j]+3] = __float2bfloat16(va.w);
        float4 vb = *(const float4*)&srcB[j][gcB[j]];
        Bsm[0][rowB[j]][gcB[j]+0] = __float2bfloat16(vb.x);
        Bsm[0][rowB[j]][gcB[j]+1] = __float2bfloat16(vb.y);
        Bsm[0][rowB[j]][gcB[j]+2] = __float2bfloat16(vb.z);
        Bsm[0][rowB[j]][gcB[j]+3] = __float2bfloat16(vb.w);
    }
    __syncthreads();

    const int NIT = DM / BKK;            // 16
    for (int kt = 0; kt < NIT; kt++) {
        const int cur = kt & 1;
        float4 av[4], bv[4];
        if (kt + 1 < NIT) {
            const int kg = (kt + 1) * BKK;
            #pragma unroll
            for (int j = 0; j < 4; j++) {
                av[j] = *(const float4*)&srcA[(size_t)rowA[j]*DM + kg + gcA[j]];
                bv[j] = *(const float4*)&srcB[j][kg + gcB[j]];
            }
        }

        #pragma unroll
        for (int kk = 0; kk < BKK; kk += 16) {
            wmma::fragment<wmma::matrix_a,16,16,16,__nv_bfloat16,wmma::row_major> af[2];
            wmma::fragment<wmma::matrix_b,16,16,16,__nv_bfloat16,wmma::col_major> bf[4];
            #pragma unroll
            for (int m = 0; m < 2; m++)
                wmma::load_matrix_sync(af[m], &As[cur][wm*32 + m*16][kk], KPAD);
            #pragma unroll
            for (int n = 0; n < 4; n++)
                wmma::load_matrix_sync(bf[n], &Bsm[cur][wn*64 + n*16][kk], KPAD);
            #pragma unroll
            for (int m = 0; m < 2; m++)
                #pragma unroll
                for (int n = 0; n < 4; n++)
                    wmma::mma_sync(acc[m][n], af[m], bf[n], acc[m][n]);
        }

        if (kt + 1 < NIT) {
            const int nxt = cur ^ 1;
            #pragma unroll
            for (int j = 0; j < 4; j++) {
                As[nxt][rowA[j]][gcA[j]+0] = __float2bfloat16(av[j].x);
                As[nxt][rowA[j]][gcA[j]+1] = __float2bfloat16(av[j].y);
                As[nxt][rowA[j]][gcA[j]+2] = __float2bfloat16(av[j].z);
                As[nxt][rowA[j]][gcA[j]+3] = __float2bfloat16(av[j].w);
                Bsm[nxt][rowB[j]][gcB[j]+0] = __float2bfloat16(bv[j].x);
                Bsm[nxt][rowB[j]][gcB[j]+1] = __float2bfloat16(bv[j].y);
                Bsm[nxt][rowB[j]][gcB[j]+2] = __float2bfloat16(bv[j].z);
                Bsm[nxt][rowB[j]][gcB[j]+3] = __float2bfloat16(bv[j].w);
            }
        }
        __syncthreads();
    }

    #pragma unroll
    for (int m = 0; m < 2; m++)
        #pragma unroll
        for (int n = 0; n < 4; n++)
            wmma::store_matrix_sync(
                &g_QK[(size_t)(bm*BM + wm*32 + m*16)*N_TOT + bn*BN + wn*64 + n*16],
                acc[m][n], N_TOT, wmma::mem_row_major);
}

// -------------------- Kernel 2: banded dot products (bias folded) --------------
__global__ __launch_bounds__(256) void band_kernel(
    const float* __restrict__ bq, const float* __restrict__ bk)
{
    int row  = blockIdx.x;               // b*SEQ + i
    int b    = row >> 10;
    int i    = row & (SEQ - 1);
    int h    = threadIdx.x >> 5;
    int lane = threadIdx.x & 31;
    int c    = h*DQ + lane*2;

    float2 qv  = *(const float2*)&g_QK[(size_t)row*N_TOT + c];
    float2 bqv = *(const float2*)&bq[c];
    float2 bkv = *(const float2*)&bk[c];
    float q0 = qv.x + bqv.x, q1 = qv.y + bqv.y;

    float sf = 0.f, sb = 0.f;
    if (i < SEQ-1) {
        float2 kv = *(const float2*)&g_QK[(size_t)(row+1)*N_TOT + DM + c];
        sf = q0*(kv.x + bkv.x) + q1*(kv.y + bkv.y);
    }
    if (i > 0) {
        float2 kv = *(const float2*)&g_QK[(size_t)(row-1)*N_TOT + DM + c];
        sb = q0*(kv.x + bkv.x) + q1*(kv.y + bkv.y);
    }
    #pragma unroll
    for (int off = 16; off; off >>= 1) {
        sf += __shfl_down_sync(0xffffffffu, sf, off);
        sb += __shfl_down_sync(0xffffffffu, sb, off);
    }
    if (lane == 0) {
        int idx = (b*NH + h)*SEQ + i;
        g_Sf[idx] = sf * (1.0f / DM);
        g_Sb[idx] = sb * (1.0f / DM);
    }
}

// -------------------- Kernel 3: softmax -> g -> block prefix scan --------------
__global__ __launch_bounds__(1024) void scan_kernel(const int* __restrict__ amask)
{
    int bh = blockIdx.x;
    int b  = bh >> 3;
    int t  = threadIdx.x;

    __shared__ float b_sh[SEQ];
    __shared__ float wsum[32];

    float sf = g_Sf[bh*SEQ + t];
    float sb = g_Sb[bh*SEQ + t];
    bool vf = (t < SEQ-1) && (amask[b*SEQ + t + 1] != 0);
    bool vb = (t > 0)     && (amask[b*SEQ + t - 1] != 0);

    float a, bb;
    if (vf | vb) {
        float m  = fmaxf(vf ? sf : -3.4e38f, vb ? sb : -3.4e38f);
        float ea = vf ? __expf(sf - m) : 0.f;
        float eb = vb ? __expf(sb - m) : 0.f;
        float den = ea + eb;
        a  = ea / den;
        bb = eb / den;
    } else {
        a = bb = 1.0f / SEQ;
    }
    b_sh[t] = bb;
    __syncthreads();

    float g = 0.f;
    if (t < SEQ-1) {
        float ph = sqrtf(a * b_sh[t+1] + 1e-9f);
        g_band[bh*SEQ + t] = ph;
        g = logf(ph + 1e-9f);
    }

    int lane = t & 31, wid = t >> 5;
    float incl = g;
    #pragma unroll
    for (int off = 1; off < 32; off <<= 1) {
        float n = __shfl_up_sync(0xffffffffu, incl, off);
        if (lane >= off) incl += n;
    }
    if (lane == 31) wsum[wid] = incl;
    __syncthreads();
    if (wid == 0) {
        float w = wsum[lane];
        #pragma unroll
        for (int off = 1; off < 32; off <<= 1) {
            float n = __shfl_up_sync(0xffffffffu, w, off);
            if (lane >= off) w += n;
        }
        wsum[lane] = w;
    }
    __syncthreads();
    float base = (wid > 0) ? wsum[wid-1] : 0.f;
    g_G[bh*SEQ + t] = base + incl - g;   // exclusive prefix: G[k] = sum_{j<k} g_j
}

// -------------------- Kernel 4: materialize outputs (R2 structure + __stcs) ----
__global__ __launch_bounds__(256) void out_kernel(float* __restrict__ out, int write_ph)
{
    const float SQRT_EPS = 3.1622776601683795e-5f;
    int row = blockIdx.x;                // bh*SEQ + i
    int bh  = row >> 10;
    int i   = row & (SEQ - 1);
    int k0  = threadIdx.x << 2;

    const float* Gp = g_G + bh*SEQ;
    float Gi = __ldg(&Gp[i]);
    float4 gk = *(const float4*)&Gp[k0];

    float4 o;
    {
        int k;
        k = k0 + 0; o.x = (k == i) ? SQRT_EPS : (__expf((k > i) ? gk.x - Gi : Gi - gk.x) + 1e-9f);
        k = k0 + 1; o.y = (k == i) ? SQRT_EPS : (__expf((k > i) ? gk.y - Gi : Gi - gk.y) + 1e-9f);
        k = k0 + 2; o.z = (k == i) ? SQRT_EPS : (__expf((k > i) ? gk.z - Gi : Gi - gk.z) + 1e-9f);
        k = k0 + 3; o.w = (k == i) ? SQRT_EPS : (__expf((k > i) ? gk.w - Gi : Gi - gk.w) + 1e-9f);
    }
    size_t off = (size_t)row * SEQ + k0;
    __stcs((float4*)(out + off), o);

    if (write_ph) {
        float4 p = make_float4(SQRT_EPS, SQRT_EPS, SQRT_EPS, SQRT_EPS);
        int d = (i - 1) - k0;
        if (d >= 0 && d < 4) {
            float v = g_band[bh*SEQ + i - 1];
            if (d == 0) p.x = v; else if (d == 1) p.y = v; else if (d == 2) p.z = v; else p.w = v;
        }
        d = (i + 1) - k0;
        if (d >= 0 && d < 4) {
            float v = g_band[bh*SEQ + i];
            if (d == 0) p.x = v; else if (d == 1) p.y = v; else if (d == 2) p.z = v; else p.w = v;
        }
        __stcs((float4*)(out + (size_t)NBH*SEQ*SEQ + off), p);
    }
}

// -------------------- launch ---------------------------------------------------
extern "C" void kernel_launch(void* const* d_in, const int* in_sizes, int n_in,
                              void* d_out, int out_size)
{
    const float* ctx   = (const float*)d_in[0];   // (4,1024,512) fp32
    const int*   amask = (const int*)  d_in[1];   // (4,1024) int32
    const float* Wq    = (const float*)d_in[2];   // (512,512)
    const float* bq    = (const float*)d_in[3];   // (512,)
    const float* Wk    = (const float*)d_in[4];   // (512,512)
    const float* bk    = (const float*)d_in[5];   // (512,)
    float* out = (float*)d_out;

    long long total = (long long)NBH * SEQ * SEQ;
    int write_ph = ((long long)out_size >= 2 * total) ? 1 : 0;

    dim3 ggrid(N_TOT / BN, M_TOT / BM);           // (8, 32)
    gemm_kernel<<<ggrid, 256>>>(ctx, Wq, Wk);
    band_kernel<<<M_TOT, 256>>>(bq, bk);
    scan_kernel<<<NBH, 1024>>>(amask);
    out_kernel<<<NBH * SEQ, 256>>>(out, write_ph);
}